// round 1
// baseline (speedup 1.0000x reference)
#include <cuda_runtime.h>
#include <cstdint>

#define N_NODES 50000
#define IN_CH 256
#define OUT_CH 128
#define N_EDGES 800000

// ---------------- scratch (static device globals; no allocation) ----------------
__device__ float g_support[N_NODES * OUT_CH];   // x @ W
__device__ float g_gate[N_NODES * OUT_CH];      // x @ Wg
__device__ float g_agg_gate[N_NODES * OUT_CH];  // SpMM(gate)
__device__ int   g_rows[N_EDGES];
__device__ int   g_cols[N_EDGES];
__device__ int   g_idx64_flag;                  // 1 = indices are int64, 0 = int32

// ---------------- dtype detection -------------------------------------------------
// If the edge index arrays are really int32, reading them as int64 combines two
// random values in [0, 50000) into v0 + v1*2^32, which is out of range unless the
// odd element is exactly 0 (p ~ 2e-5 per sample). 32 samples -> effectively certain.
__global__ void detect_kernel(const void* rows, const void* cols) {
    const long long* r64 = (const long long*)rows;
    const long long* c64 = (const long long*)cols;
    int ok = 1;
    for (int i = 0; i < 16; i++) {
        long long a = r64[i], b = c64[i];
        if (a < 0 || a >= N_NODES) ok = 0;
        if (b < 0 || b >= N_NODES) ok = 0;
    }
    g_idx64_flag = ok;
}

__global__ void convert_kernel(const void* rows, const void* cols) {
    int i = blockIdx.x * blockDim.x + threadIdx.x;
    if (i >= N_EDGES) return;
    if (g_idx64_flag) {
        g_rows[i] = (int)((const long long*)rows)[i];
        g_cols[i] = (int)((const long long*)cols)[i];
    } else {
        g_rows[i] = ((const int*)rows)[i];
        g_cols[i] = ((const int*)cols)[i];
    }
}

// ---------------- fused dual GEMM: support = xW, gate = xWg -----------------------
// BM=32 rows/block, full 128 output cols, BK=32. 256 threads: tid%32 = row,
// tid/32 = 16-col group. Weight smem reads are warp-broadcast (all lanes in a
// warp share the col group), xs reads are conflict-free (stride 33).
__global__ __launch_bounds__(256) void gemm_kernel(const float* __restrict__ x,
                                                   const float* __restrict__ W,
                                                   const float* __restrict__ Wg) {
    __shared__ float xs[32][33];
    __shared__ float ws[32][OUT_CH];
    __shared__ float wgs[32][OUT_CH];

    const int tid  = threadIdx.x;
    const int row  = tid & 31;
    const int cg   = tid >> 5;         // 0..7
    const int col0 = cg * 16;
    const int row0 = blockIdx.x * 32;

    float acc_s[16], acc_g[16];
#pragma unroll
    for (int j = 0; j < 16; j++) { acc_s[j] = 0.f; acc_g[j] = 0.f; }

    for (int k0 = 0; k0 < IN_CH; k0 += 32) {
        // load x tile 32x32 (float4 per thread)
        {
            int lr = tid >> 3;
            int lc = (tid & 7) << 2;
            int gr = row0 + lr;
            float4 xv = make_float4(0.f, 0.f, 0.f, 0.f);
            if (gr < N_NODES) xv = *(const float4*)&x[(size_t)gr * IN_CH + k0 + lc];
            xs[lr][lc] = xv.x; xs[lr][lc + 1] = xv.y;
            xs[lr][lc + 2] = xv.z; xs[lr][lc + 3] = xv.w;
        }
        // load W / Wg tiles 32x128 (4 float4 per thread each)
#pragma unroll
        for (int j = 0; j < 4; j++) {
            int e  = tid + j * 256;     // float4 index into 1024 float4s
            int kr = e >> 5;
            int kc = (e & 31) << 2;
            *(float4*)&ws[kr][kc]  = *(const float4*)&W[(size_t)(k0 + kr) * OUT_CH + kc];
            *(float4*)&wgs[kr][kc] = *(const float4*)&Wg[(size_t)(k0 + kr) * OUT_CH + kc];
        }
        __syncthreads();

#pragma unroll
        for (int k = 0; k < 32; k++) {
            float a = xs[row][k];
            const float4* wp  = (const float4*)&ws[k][col0];
            const float4* wgp = (const float4*)&wgs[k][col0];
#pragma unroll
            for (int q = 0; q < 4; q++) {
                float4 wv  = wp[q];
                float4 wgv = wgp[q];
                acc_s[q * 4 + 0] += a * wv.x;  acc_s[q * 4 + 1] += a * wv.y;
                acc_s[q * 4 + 2] += a * wv.z;  acc_s[q * 4 + 3] += a * wv.w;
                acc_g[q * 4 + 0] += a * wgv.x; acc_g[q * 4 + 1] += a * wgv.y;
                acc_g[q * 4 + 2] += a * wgv.z; acc_g[q * 4 + 3] += a * wgv.w;
            }
        }
        __syncthreads();
    }

    const int r = row0 + row;
    if (r < N_NODES) {
        float4* sp = (float4*)&g_support[(size_t)r * OUT_CH + col0];
        float4* gp = (float4*)&g_gate[(size_t)r * OUT_CH + col0];
#pragma unroll
        for (int q = 0; q < 4; q++) {
            sp[q] = make_float4(acc_s[q * 4 + 0], acc_s[q * 4 + 1],
                                acc_s[q * 4 + 2], acc_s[q * 4 + 3]);
            gp[q] = make_float4(acc_g[q * 4 + 0], acc_g[q * 4 + 1],
                                acc_g[q * 4 + 2], acc_g[q * 4 + 3]);
        }
    }
}

// ---------------- edge scatter: one warp per edge ---------------------------------
__device__ __forceinline__ void red_add_v4(float* addr, float4 v) {
    asm volatile("red.global.add.v4.f32 [%0], {%1, %2, %3, %4};"
                 :: "l"(addr), "f"(v.x), "f"(v.y), "f"(v.z), "f"(v.w)
                 : "memory");
}

__global__ __launch_bounds__(256) void scatter_kernel(const float* __restrict__ vals,
                                                      float* __restrict__ agg_support) {
    const int warp = (blockIdx.x * blockDim.x + threadIdx.x) >> 5;
    const int lane = threadIdx.x & 31;
    if (warp >= N_EDGES) return;

    const int   r = g_rows[warp];
    const int   c = g_cols[warp];
    const float v = __ldg(&vals[warp]);

    const size_t src = (size_t)c * OUT_CH + lane * 4;
    const size_t dst = (size_t)r * OUT_CH + lane * 4;

    float4 s  = *(const float4*)&g_support[src];
    float4 gt = *(const float4*)&g_gate[src];
    s.x *= v;  s.y *= v;  s.z *= v;  s.w *= v;
    gt.x *= v; gt.y *= v; gt.z *= v; gt.w *= v;

    red_add_v4(&agg_support[dst], s);
    red_add_v4(&g_agg_gate[dst], gt);
}

// ---------------- final fuse: out = sigmoid(agg_gate) * agg_support --------------
__global__ __launch_bounds__(256) void final_kernel(float* __restrict__ out) {
    int i = blockIdx.x * blockDim.x + threadIdx.x;
    const int total4 = N_NODES * OUT_CH / 4;
    if (i >= total4) return;
    float4 s = ((const float4*)out)[i];
    float4 g = ((const float4*)g_agg_gate)[i];
    s.x *= 1.f / (1.f + __expf(-g.x));
    s.y *= 1.f / (1.f + __expf(-g.y));
    s.z *= 1.f / (1.f + __expf(-g.z));
    s.w *= 1.f / (1.f + __expf(-g.w));
    ((float4*)out)[i] = s;
}

// ---------------- launch ----------------------------------------------------------
extern "C" void kernel_launch(void* const* d_in, const int* in_sizes, int n_in,
                              void* d_out, int out_size) {
    const float* x     = (const float*)d_in[0];
    const void*  erows = d_in[1];
    const void*  ecols = d_in[2];
    const float* evals = (const float*)d_in[3];
    const float* W     = (const float*)d_in[4];
    const float* Wg    = (const float*)d_in[5];
    float* out = (float*)d_out;

    detect_kernel<<<1, 1>>>(erows, ecols);
    convert_kernel<<<(N_EDGES + 255) / 256, 256>>>(erows, ecols);

    gemm_kernel<<<(N_NODES + 31) / 32, 256>>>(x, W, Wg);

    void* aggp = nullptr;
    cudaGetSymbolAddress(&aggp, g_agg_gate);
    cudaMemsetAsync(d_out, 0, (size_t)N_NODES * OUT_CH * sizeof(float), 0);
    cudaMemsetAsync(aggp, 0, (size_t)N_NODES * OUT_CH * sizeof(float), 0);

    // one warp per edge: 800000 warps -> 100000 blocks of 8 warps
    scatter_kernel<<<N_EDGES / 8, 256>>>(evals, out);

    final_kernel<<<(N_NODES * OUT_CH / 4 + 255) / 256, 256>>>(out);
}

// round 2
// speedup vs baseline: 1.2724x; 1.2724x over previous
#include <cuda_runtime.h>
#include <cstdint>

#define N_NODES 50000
#define IN_CH 256
#define OUT_CH 128
#define N_EDGES 800000

typedef unsigned long long u64;

// ---------------- scratch (static device globals; no allocation) ----------------
__device__ float    g_support[N_NODES * OUT_CH];   // x @ W
__device__ float    g_gate[N_NODES * OUT_CH];      // x @ Wg
__device__ int      g_rows[N_EDGES];
__device__ int      g_cols[N_EDGES];
__device__ unsigned g_cnt[N_NODES];                // per-row degree
__device__ unsigned g_rowptr[N_NODES + 1];         // CSR row pointers
__device__ unsigned g_cursor[N_NODES];             // fill cursors
__device__ int      g_csr_col[N_EDGES];            // cols in CSR order
__device__ float    g_csr_val[N_EDGES];            // vals in CSR order
__device__ int      g_idx64_flag;

// ---------------- f32x2 packed math helpers --------------------------------------
__device__ __forceinline__ u64 pack2(float x) {
    u64 r; asm("mov.b64 %0, {%1, %1};" : "=l"(r) : "f"(x)); return r;
}
__device__ __forceinline__ void ffma2(u64& d, u64 a, u64 b) {
    asm("fma.rn.f32x2 %0, %1, %2, %0;" : "+l"(d) : "l"(a), "l"(b));
}
__device__ __forceinline__ float2 unpack2(u64 v) {
    float2 r; asm("mov.b64 {%0, %1}, %2;" : "=f"(r.x), "=f"(r.y) : "l"(v)); return r;
}

// ---------------- index dtype detection -------------------------------------------
__global__ void detect_kernel(const void* rows, const void* cols) {
    const long long* r64 = (const long long*)rows;
    const long long* c64 = (const long long*)cols;
    int ok = 1;
    for (int i = 0; i < 16; i++) {
        long long a = r64[i], b = c64[i];
        if (a < 0 || a >= N_NODES) ok = 0;
        if (b < 0 || b >= N_NODES) ok = 0;
    }
    g_idx64_flag = ok;
}

// convert indices + histogram of row degrees
__global__ __launch_bounds__(256) void count_kernel(const void* rows, const void* cols) {
    int i = blockIdx.x * blockDim.x + threadIdx.x;
    if (i >= N_EDGES) return;
    int r, c;
    if (g_idx64_flag) {
        r = (int)((const long long*)rows)[i];
        c = (int)((const long long*)cols)[i];
    } else {
        r = ((const int*)rows)[i];
        c = ((const int*)cols)[i];
    }
    g_rows[i] = r;
    g_cols[i] = c;
    atomicAdd(&g_cnt[r], 1u);
}

// single-block exclusive scan of g_cnt -> g_rowptr, g_cursor
#define SCAN_THREADS 512
#define SCAN_PER_THREAD 98     // 512*98 = 50176 >= 50000
__global__ __launch_bounds__(SCAN_THREADS) void scan_kernel() {
    __shared__ unsigned sums[SCAN_THREADS];
    const int t = threadIdx.x;
    const int base = t * SCAN_PER_THREAD;
    unsigned s = 0;
    for (int i = 0; i < SCAN_PER_THREAD; i++) {
        int idx = base + i;
        if (idx < N_NODES) s += g_cnt[idx];
    }
    sums[t] = s;
    __syncthreads();
    // Hillis-Steele inclusive scan over 512 partials
    for (int off = 1; off < SCAN_THREADS; off <<= 1) {
        unsigned v = (t >= off) ? sums[t - off] : 0u;
        __syncthreads();
        sums[t] += v;
        __syncthreads();
    }
    unsigned run = (t == 0) ? 0u : sums[t - 1];
    for (int i = 0; i < SCAN_PER_THREAD; i++) {
        int idx = base + i;
        if (idx < N_NODES) {
            g_rowptr[idx] = run;
            g_cursor[idx] = run;
            run += g_cnt[idx];
        }
    }
    if (t == SCAN_THREADS - 1) g_rowptr[N_NODES] = run;
}

// scatter edges into CSR slots
__global__ __launch_bounds__(256) void fill_kernel(const float* __restrict__ vals) {
    int i = blockIdx.x * blockDim.x + threadIdx.x;
    if (i >= N_EDGES) return;
    int r = g_rows[i];
    unsigned pos = atomicAdd(&g_cursor[r], 1u);
    g_csr_col[pos] = g_cols[i];
    g_csr_val[pos] = vals[i];
}

// ---------------- fused dual GEMM: support = xW, gate = xWg -----------------------
// BM=64, BN=128(full), BK=32. 256 threads. Each thread: 2 rows x 16 cols x 2 mats,
// accumulated as packed f32x2 (full-rate FMA pipe on sm_100a).
__global__ __launch_bounds__(256) void gemm_kernel(const float* __restrict__ x,
                                                   const float* __restrict__ W,
                                                   const float* __restrict__ Wg) {
    __shared__ float xs[64][33];
    __shared__ float ws[32][OUT_CH];
    __shared__ float wgs[32][OUT_CH];

    const int tid  = threadIdx.x;
    const int row  = tid & 31;         // owns rows row and row+32
    const int cg   = tid >> 5;         // 0..7 col groups of 16
    const int col0 = cg * 16;
    const int row0 = blockIdx.x * 64;

    u64 accS[2][8], accG[2][8];
#pragma unroll
    for (int rp = 0; rp < 2; rp++)
#pragma unroll
        for (int q = 0; q < 8; q++) { accS[rp][q] = 0ull; accG[rp][q] = 0ull; }

    for (int k0 = 0; k0 < IN_CH; k0 += 32) {
        // x tile: 64x32 floats = 512 float4, 2 per thread
#pragma unroll
        for (int j = 0; j < 2; j++) {
            int e  = tid + j * 256;
            int lr = e >> 3;
            int lc = (e & 7) << 2;
            int gr = row0 + lr;
            float4 xv = make_float4(0.f, 0.f, 0.f, 0.f);
            if (gr < N_NODES) xv = *(const float4*)&x[(size_t)gr * IN_CH + k0 + lc];
            xs[lr][lc] = xv.x; xs[lr][lc + 1] = xv.y;
            xs[lr][lc + 2] = xv.z; xs[lr][lc + 3] = xv.w;
        }
        // W / Wg tiles 32x128: 4 float4 per thread each
#pragma unroll
        for (int j = 0; j < 4; j++) {
            int e  = tid + j * 256;
            int kr = e >> 5;
            int kc = (e & 31) << 2;
            *(float4*)&ws[kr][kc]  = *(const float4*)&W[(size_t)(k0 + kr) * OUT_CH + kc];
            *(float4*)&wgs[kr][kc] = *(const float4*)&Wg[(size_t)(k0 + kr) * OUT_CH + kc];
        }
        __syncthreads();

#pragma unroll
        for (int k = 0; k < 32; k++) {
            u64 a0 = pack2(xs[row][k]);
            u64 a1 = pack2(xs[row + 32][k]);
            const ulonglong2* wp  = (const ulonglong2*)&ws[k][col0];   // broadcast
            const ulonglong2* wgp = (const ulonglong2*)&wgs[k][col0];
#pragma unroll
            for (int q = 0; q < 4; q++) {
                ulonglong2 wv  = wp[q];
                ulonglong2 wgv = wgp[q];
                ffma2(accS[0][q * 2],     a0, wv.x);
                ffma2(accS[0][q * 2 + 1], a0, wv.y);
                ffma2(accS[1][q * 2],     a1, wv.x);
                ffma2(accS[1][q * 2 + 1], a1, wv.y);
                ffma2(accG[0][q * 2],     a0, wgv.x);
                ffma2(accG[0][q * 2 + 1], a0, wgv.y);
                ffma2(accG[1][q * 2],     a1, wgv.x);
                ffma2(accG[1][q * 2 + 1], a1, wgv.y);
            }
        }
        __syncthreads();
    }

#pragma unroll
    for (int rp = 0; rp < 2; rp++) {
        const int r = row0 + row + rp * 32;
        if (r >= N_NODES) continue;
        float4* sp = (float4*)&g_support[(size_t)r * OUT_CH + col0];
        float4* gp = (float4*)&g_gate[(size_t)r * OUT_CH + col0];
#pragma unroll
        for (int q4 = 0; q4 < 4; q4++) {
            float2 s0 = unpack2(accS[rp][q4 * 2]);
            float2 s1 = unpack2(accS[rp][q4 * 2 + 1]);
            float2 g0 = unpack2(accG[rp][q4 * 2]);
            float2 g1 = unpack2(accG[rp][q4 * 2 + 1]);
            sp[q4] = make_float4(s0.x, s0.y, s1.x, s1.y);
            gp[q4] = make_float4(g0.x, g0.y, g1.x, g1.y);
        }
    }
}

// ---------------- fused row SpMM + sigmoid gate: one warp per row -----------------
__global__ __launch_bounds__(256) void spmm_kernel(float* __restrict__ out) {
    const int warp = (blockIdx.x * blockDim.x + threadIdx.x) >> 5;
    const int lane = threadIdx.x & 31;
    if (warp >= N_NODES) return;

    const int start = g_rowptr[warp];
    const int end   = g_rowptr[warp + 1];

    float4 aS = make_float4(0.f, 0.f, 0.f, 0.f);
    float4 aG = make_float4(0.f, 0.f, 0.f, 0.f);

    for (int e0 = start; e0 < end; e0 += 32) {
        const int n = min(32, end - e0);
        int   c = 0;
        float v = 0.f;
        if (lane < n) { c = g_csr_col[e0 + lane]; v = g_csr_val[e0 + lane]; }

        int j = 0;
        // 2-wide software pipeline: 4 independent LDG.128 in flight per step
        for (; j + 2 <= n; j += 2) {
            int   c0 = __shfl_sync(0xffffffffu, c, j);
            int   c1 = __shfl_sync(0xffffffffu, c, j + 1);
            float v0 = __shfl_sync(0xffffffffu, v, j);
            float v1 = __shfl_sync(0xffffffffu, v, j + 1);
            size_t o0 = (size_t)c0 * OUT_CH + lane * 4;
            size_t o1 = (size_t)c1 * OUT_CH + lane * 4;
            float4 s0 = *(const float4*)&g_support[o0];
            float4 g0 = *(const float4*)&g_gate[o0];
            float4 s1 = *(const float4*)&g_support[o1];
            float4 g1 = *(const float4*)&g_gate[o1];
            aS.x += v0 * s0.x; aS.y += v0 * s0.y; aS.z += v0 * s0.z; aS.w += v0 * s0.w;
            aG.x += v0 * g0.x; aG.y += v0 * g0.y; aG.z += v0 * g0.z; aG.w += v0 * g0.w;
            aS.x += v1 * s1.x; aS.y += v1 * s1.y; aS.z += v1 * s1.z; aS.w += v1 * s1.w;
            aG.x += v1 * g1.x; aG.y += v1 * g1.y; aG.z += v1 * g1.z; aG.w += v1 * g1.w;
        }
        if (j < n) {
            int   c0 = __shfl_sync(0xffffffffu, c, j);
            float v0 = __shfl_sync(0xffffffffu, v, j);
            size_t o0 = (size_t)c0 * OUT_CH + lane * 4;
            float4 s0 = *(const float4*)&g_support[o0];
            float4 g0 = *(const float4*)&g_gate[o0];
            aS.x += v0 * s0.x; aS.y += v0 * s0.y; aS.z += v0 * s0.z; aS.w += v0 * s0.w;
            aG.x += v0 * g0.x; aG.y += v0 * g0.y; aG.z += v0 * g0.z; aG.w += v0 * g0.w;
        }
    }

    float4 o;
    o.x = aS.x / (1.f + __expf(-aG.x));
    o.y = aS.y / (1.f + __expf(-aG.y));
    o.z = aS.z / (1.f + __expf(-aG.z));
    o.w = aS.w / (1.f + __expf(-aG.w));
    *(float4*)&out[(size_t)warp * OUT_CH + lane * 4] = o;
}

// ---------------- launch ----------------------------------------------------------
extern "C" void kernel_launch(void* const* d_in, const int* in_sizes, int n_in,
                              void* d_out, int out_size) {
    const float* x     = (const float*)d_in[0];
    const void*  erows = d_in[1];
    const void*  ecols = d_in[2];
    const float* evals = (const float*)d_in[3];
    const float* W     = (const float*)d_in[4];
    const float* Wg    = (const float*)d_in[5];
    float* out = (float*)d_out;

    void* cntp = nullptr;
    cudaGetSymbolAddress(&cntp, g_cnt);
    cudaMemsetAsync(cntp, 0, (size_t)N_NODES * sizeof(unsigned), 0);

    detect_kernel<<<1, 1>>>(erows, ecols);
    count_kernel<<<(N_EDGES + 255) / 256, 256>>>(erows, ecols);
    scan_kernel<<<1, SCAN_THREADS>>>();
    fill_kernel<<<(N_EDGES + 255) / 256, 256>>>(evals);

    gemm_kernel<<<(N_NODES + 63) / 64, 256>>>(x, W, Wg);

    // one warp per row: 50000 warps -> 6250 blocks of 8 warps
    spmm_kernel<<<(N_NODES + 7) / 8, 256>>>(out);
}

// round 4
// speedup vs baseline: 1.8611x; 1.4627x over previous
#include <cuda_runtime.h>
#include <cstdint>

#define N_NODES 50000
#define IN_CH 256
#define OUT_CH 128
#define N_EDGES 800000

typedef unsigned long long u64;
typedef unsigned int u32;

// ---------------- scratch (static device globals; no allocation) ----------------
__device__ float    g_support[N_NODES * OUT_CH];   // x @ W
__device__ float    g_gate[N_NODES * OUT_CH];      // x @ Wg
__device__ u32      g_wt[256 * 256];               // combined [W|Wg]^T, tf32-rounded, [n][k]
__device__ int      g_rows[N_EDGES];
__device__ int      g_cols[N_EDGES];
__device__ unsigned g_cnt[N_NODES];
__device__ unsigned g_rowptr[N_NODES + 1];
__device__ unsigned g_cursor[N_NODES];
__device__ int      g_csr_col[N_EDGES];
__device__ float    g_csr_val[N_EDGES];
__device__ int      g_idx64_flag;

__device__ __forceinline__ u32 f2tf32(float f) {
    u32 r; asm("cvt.rna.tf32.f32 %0, %1;" : "=r"(r) : "f"(f)); return r;
}

// ---------------- index dtype detection -------------------------------------------
__global__ void detect_kernel(const void* rows, const void* cols) {
    const long long* r64 = (const long long*)rows;
    const long long* c64 = (const long long*)cols;
    int ok = 1;
    for (int i = 0; i < 16; i++) {
        long long a = r64[i], b = c64[i];
        if (a < 0 || a >= N_NODES) ok = 0;
        if (b < 0 || b >= N_NODES) ok = 0;
    }
    g_idx64_flag = ok;
}

__global__ __launch_bounds__(256) void count_kernel(const void* rows, const void* cols) {
    int i = blockIdx.x * blockDim.x + threadIdx.x;
    if (i >= N_EDGES) return;
    int r, c;
    if (g_idx64_flag) {
        r = (int)((const long long*)rows)[i];
        c = (int)((const long long*)cols)[i];
    } else {
        r = ((const int*)rows)[i];
        c = ((const int*)cols)[i];
    }
    g_rows[i] = r;
    g_cols[i] = c;
    atomicAdd(&g_cnt[r], 1u);
}

#define SCAN_THREADS 512
#define SCAN_PER_THREAD 98
__global__ __launch_bounds__(SCAN_THREADS) void scan_kernel() {
    __shared__ unsigned sums[SCAN_THREADS];
    const int t = threadIdx.x;
    const int base = t * SCAN_PER_THREAD;
    unsigned s = 0;
    for (int i = 0; i < SCAN_PER_THREAD; i++) {
        int idx = base + i;
        if (idx < N_NODES) s += g_cnt[idx];
    }
    sums[t] = s;
    __syncthreads();
    for (int off = 1; off < SCAN_THREADS; off <<= 1) {
        unsigned v = (t >= off) ? sums[t - off] : 0u;
        __syncthreads();
        sums[t] += v;
        __syncthreads();
    }
    unsigned run = (t == 0) ? 0u : sums[t - 1];
    for (int i = 0; i < SCAN_PER_THREAD; i++) {
        int idx = base + i;
        if (idx < N_NODES) {
            g_rowptr[idx] = run;
            g_cursor[idx] = run;
            run += g_cnt[idx];
        }
    }
    if (t == SCAN_THREADS - 1) g_rowptr[N_NODES] = run;
}

__global__ __launch_bounds__(256) void fill_kernel(const float* __restrict__ vals) {
    int i = blockIdx.x * blockDim.x + threadIdx.x;
    if (i >= N_EDGES) return;
    int r = g_rows[i];
    unsigned pos = atomicAdd(&g_cursor[r], 1u);
    g_csr_col[pos] = g_cols[i];
    g_csr_val[pos] = vals[i];
}

// ---------------- weight transpose + tf32 round: Wt[n][k] -------------------------
__global__ __launch_bounds__(256) void wprep_kernel(const float* __restrict__ W,
                                                    const float* __restrict__ Wg) {
    int i = blockIdx.x * blockDim.x + threadIdx.x;   // 65536 elements
    if (i >= 256 * 256) return;
    int n = i >> 8;          // 0..255 output col
    int k = i & 255;         // 0..255 input ch
    float v = (n < 128) ? W[(size_t)k * OUT_CH + n] : Wg[(size_t)k * OUT_CH + (n - 128)];
    g_wt[(size_t)n * 256 + k] = f2tf32(v);
}

// ---------------- mma.sync tf32 dual GEMM -----------------------------------------
// CTA: 512 threads = 16 warps (4 M x 4 N). CTA tile M=128, N=256 (N<128 -> support,
// N>=128 -> gate). Warp tile 32x64 = 2 x 8 mma tiles of m16n8k8. K chunked by 16.
#define KC 16
#define AST 20                 // padded k-stride for A smem
#define BST 20                 // padded k-stride for B smem

__device__ __forceinline__ void mma_tf32(float c[4], const u32 a[4], const u32 b[2]) {
    asm volatile(
        "mma.sync.aligned.m16n8k8.row.col.f32.tf32.tf32.f32 "
        "{%0,%1,%2,%3}, {%4,%5,%6,%7}, {%8,%9}, {%0,%1,%2,%3};"
        : "+f"(c[0]), "+f"(c[1]), "+f"(c[2]), "+f"(c[3])
        : "r"(a[0]), "r"(a[1]), "r"(a[2]), "r"(a[3]), "r"(b[0]), "r"(b[1]));
}

__global__ __launch_bounds__(512) void gemm_kernel(const float* __restrict__ x) {
    __shared__ u32 As[128 * AST];   // [m][k] tf32
    __shared__ u32 Bs[256 * BST];   // [n][k] tf32

    const int tid    = threadIdx.x;
    const int wid    = tid >> 5;
    const int lane   = tid & 31;
    const int gid    = lane >> 2;   // group id 0..7
    const int tig    = lane & 3;    // thread in group 0..3
    const int warp_m = wid & 3;     // 0..3 -> m offset *32
    const int warp_n = wid >> 2;    // 0..3 -> n offset *64
    const int row0   = blockIdx.x * 128;

    float c[2][8][4];
#pragma unroll
    for (int mt = 0; mt < 2; mt++)
#pragma unroll
        for (int nt = 0; nt < 8; nt++)
#pragma unroll
            for (int q = 0; q < 4; q++) c[mt][nt][q] = 0.f;

    for (int k0 = 0; k0 < IN_CH; k0 += KC) {
        __syncthreads();
        // load A: 128 rows x 16 k = 512 float4, 1 per thread (tf32 round)
        {
            int m  = tid >> 2;
            int kk = (tid & 3) << 2;
            int gr = row0 + m;
            uint4 v = make_uint4(0u, 0u, 0u, 0u);
            if (gr < N_NODES) {
                float4 xv = *(const float4*)&x[(size_t)gr * IN_CH + k0 + kk];
                v.x = f2tf32(xv.x); v.y = f2tf32(xv.y);
                v.z = f2tf32(xv.z); v.w = f2tf32(xv.w);
            }
            *(uint4*)&As[m * AST + kk] = v;
        }
        // load B: 256 rows(n) x 16 k = 1024 float4, 2 per thread
#pragma unroll
        for (int j = 0; j < 2; j++) {
            int e  = tid + j * 512;
            int n  = e >> 2;
            int kk = (e & 3) << 2;
            *(uint4*)&Bs[n * BST + kk] = *(const uint4*)&g_wt[(size_t)n * 256 + k0 + kk];
        }
        __syncthreads();

#pragma unroll
        for (int ks = 0; ks < KC / 8; ks++) {
            const int k = ks * 8;
            u32 a[2][4];
#pragma unroll
            for (int mt = 0; mt < 2; mt++) {
                const int m = warp_m * 32 + mt * 16;
                a[mt][0] = As[(m + gid) * AST + k + tig];
                a[mt][1] = As[(m + gid + 8) * AST + k + tig];
                a[mt][2] = As[(m + gid) * AST + k + tig + 4];
                a[mt][3] = As[(m + gid + 8) * AST + k + tig + 4];
            }
#pragma unroll
            for (int nt = 0; nt < 8; nt++) {
                const int n = warp_n * 64 + nt * 8;
                u32 b[2];
                b[0] = Bs[(n + gid) * BST + k + tig];
                b[1] = Bs[(n + gid) * BST + k + tig + 4];
                mma_tf32(c[0][nt], a[0], b);
                mma_tf32(c[1][nt], a[1], b);
            }
        }
    }

    // epilogue: c0/c1 -> (row gid, cols 2tig,2tig+1); c2/c3 -> row gid+8
#pragma unroll
    for (int mt = 0; mt < 2; mt++) {
        const int m = row0 + warp_m * 32 + mt * 16 + gid;
#pragma unroll
        for (int nt = 0; nt < 8; nt++) {
            const int n = warp_n * 64 + nt * 8 + 2 * tig;
            float* const dstbase = (n < 128) ? g_support : g_gate;
            const int nc = n & 127;
            if (m < N_NODES)
                *(float2*)&dstbase[(size_t)m * OUT_CH + nc] =
                    make_float2(c[mt][nt][0], c[mt][nt][1]);
            if (m + 8 < N_NODES)
                *(float2*)&dstbase[(size_t)(m + 8) * OUT_CH + nc] =
                    make_float2(c[mt][nt][2], c[mt][nt][3]);
        }
    }
}

// ---------------- fused row SpMM + sigmoid gate: one warp per row -----------------
__global__ __launch_bounds__(256) void spmm_kernel(float* __restrict__ out) {
    const int warp = (blockIdx.x * blockDim.x + threadIdx.x) >> 5;
    const int lane = threadIdx.x & 31;
    if (warp >= N_NODES) return;

    const int start = g_rowptr[warp];
    const int end   = g_rowptr[warp + 1];

    float4 aS = make_float4(0.f, 0.f, 0.f, 0.f);
    float4 aG = make_float4(0.f, 0.f, 0.f, 0.f);

    for (int e0 = start; e0 < end; e0 += 32) {
        const int n = min(32, end - e0);
        int   c = 0;
        float v = 0.f;
        if (lane < n) { c = __ldg(&g_csr_col[e0 + lane]); v = __ldg(&g_csr_val[e0 + lane]); }

        int j = 0;
        for (; j + 4 <= n; j += 4) {
            int   c0 = __shfl_sync(0xffffffffu, c, j);
            int   c1 = __shfl_sync(0xffffffffu, c, j + 1);
            int   c2 = __shfl_sync(0xffffffffu, c, j + 2);
            int   c3 = __shfl_sync(0xffffffffu, c, j + 3);
            float v0 = __shfl_sync(0xffffffffu, v, j);
            float v1 = __shfl_sync(0xffffffffu, v, j + 1);
            float v2 = __shfl_sync(0xffffffffu, v, j + 2);
            float v3 = __shfl_sync(0xffffffffu, v, j + 3);
            size_t o0 = (size_t)c0 * OUT_CH + lane * 4;
            size_t o1 = (size_t)c1 * OUT_CH + lane * 4;
            size_t o2 = (size_t)c2 * OUT_CH + lane * 4;
            size_t o3 = (size_t)c3 * OUT_CH + lane * 4;
            float4 s0 = *(const float4*)&g_support[o0];
            float4 g0 = *(const float4*)&g_gate[o0];
            float4 s1 = *(const float4*)&g_support[o1];
            float4 g1 = *(const float4*)&g_gate[o1];
            float4 s2 = *(const float4*)&g_support[o2];
            float4 g2 = *(const float4*)&g_gate[o2];
            float4 s3 = *(const float4*)&g_support[o3];
            float4 g3 = *(const float4*)&g_gate[o3];
            aS.x += v0 * s0.x; aS.y += v0 * s0.y; aS.z += v0 * s0.z; aS.w += v0 * s0.w;
            aG.x += v0 * g0.x; aG.y += v0 * g0.y; aG.z += v0 * g0.z; aG.w += v0 * g0.w;
            aS.x += v1 * s1.x; aS.y += v1 * s1.y; aS.z += v1 * s1.z; aS.w += v1 * s1.w;
            aG.x += v1 * g1.x; aG.y += v1 * g1.y; aG.z += v1 * g1.z; aG.w += v1 * g1.w;
            aS.x += v2 * s2.x; aS.y += v2 * s2.y; aS.z += v2 * s2.z; aS.w += v2 * s2.w;
            aG.x += v2 * g2.x; aG.y += v2 * g2.y; aG.z += v2 * g2.z; aG.w += v2 * g2.w;
            aS.x += v3 * s3.x; aS.y += v3 * s3.y; aS.z += v3 * s3.z; aS.w += v3 * s3.w;
            aG.x += v3 * g3.x; aG.y += v3 * g3.y; aG.z += v3 * g3.z; aG.w += v3 * g3.w;
        }
        for (; j < n; j++) {
            int   c0 = __shfl_sync(0xffffffffu, c, j);
            float v0 = __shfl_sync(0xffffffffu, v, j);
            size_t o0 = (size_t)c0 * OUT_CH + lane * 4;
            float4 s0 = *(const float4*)&g_support[o0];
            float4 g0 = *(const float4*)&g_gate[o0];
            aS.x += v0 * s0.x; aS.y += v0 * s0.y; aS.z += v0 * s0.z; aS.w += v0 * s0.w;
            aG.x += v0 * g0.x; aG.y += v0 * g0.y; aG.z += v0 * g0.z; aG.w += v0 * g0.w;
        }
    }

    float4 o;
    o.x = aS.x / (1.f + __expf(-aG.x));
    o.y = aS.y / (1.f + __expf(-aG.y));
    o.z = aS.z / (1.f + __expf(-aG.z));
    o.w = aS.w / (1.f + __expf(-aG.w));
    *(float4*)&out[(size_t)warp * OUT_CH + lane * 4] = o;
}

// ---------------- launch ----------------------------------------------------------
extern "C" void kernel_launch(void* const* d_in, const int* in_sizes, int n_in,
                              void* d_out, int out_size) {
    const float* x     = (const float*)d_in[0];
    const void*  erows = d_in[1];
    const void*  ecols = d_in[2];
    const float* evals = (const float*)d_in[3];
    const float* W     = (const float*)d_in[4];
    const float* Wg    = (const float*)d_in[5];
    float* out = (float*)d_out;

    void* cntp = nullptr;
    cudaGetSymbolAddress(&cntp, g_cnt);
    cudaMemsetAsync(cntp, 0, (size_t)N_NODES * sizeof(unsigned), 0);

    detect_kernel<<<1, 1>>>(erows, ecols);
    count_kernel<<<(N_EDGES + 255) / 256, 256>>>(erows, ecols);
    scan_kernel<<<1, SCAN_THREADS>>>();
    fill_kernel<<<(N_EDGES + 255) / 256, 256>>>(evals);

    wprep_kernel<<<(256 * 256 + 255) / 256, 256>>>(W, Wg);
    gemm_kernel<<<(N_NODES + 127) / 128, 512>>>(x);

    spmm_kernel<<<(N_NODES + 7) / 8, 256>>>(out);
}

// round 5
// speedup vs baseline: 1.9923x; 1.0705x over previous
#include <cuda_runtime.h>
#include <cuda_fp16.h>
#include <cstdint>

#define N_NODES 50000
#define IN_CH 256
#define OUT_CH 128
#define N_EDGES 800000

typedef unsigned long long u64;
typedef unsigned int u32;

// ---------------- scratch (static device globals; no allocation) ----------------
// g_sg layout: per node, 32 chunks of 16B; chunk j = {s[4j..4j+3], g[4j..4j+3]} fp16.
// half2 units: node row = 128 half2; chunk j at [j*4 .. j*4+3] = {s01,s23,g01,g23}.
__device__ half2    g_sg[(size_t)N_NODES * 128];
__device__ u32      g_wt[256 * 256];               // combined [W|Wg]^T, tf32-rounded, [n][k]
__device__ int      g_rows[N_EDGES];
__device__ int      g_cols[N_EDGES];
__device__ unsigned g_cnt[N_NODES];
__device__ unsigned g_rowptr[N_NODES + 1];
__device__ unsigned g_cursor[N_NODES];
__device__ int2     g_csr[N_EDGES];                // (col, val-as-int) in CSR order
__device__ int      g_idx64_flag;

__device__ __forceinline__ u32 f2tf32(float f) {
    u32 r; asm("cvt.rna.tf32.f32 %0, %1;" : "=r"(r) : "f"(f)); return r;
}

// ---------------- init: zero g_cnt + index dtype detection ------------------------
__global__ __launch_bounds__(256) void init_kernel(const void* rows, const void* cols) {
    int i = blockIdx.x * blockDim.x + threadIdx.x;
    if (i < N_NODES) g_cnt[i] = 0u;
    if (i == 0) {
        const long long* r64 = (const long long*)rows;
        const long long* c64 = (const long long*)cols;
        int ok = 1;
        for (int j = 0; j < 16; j++) {
            long long a = r64[j], b = c64[j];
            if (a < 0 || a >= N_NODES) ok = 0;
            if (b < 0 || b >= N_NODES) ok = 0;
        }
        g_idx64_flag = ok;
    }
}

__global__ __launch_bounds__(256) void count_kernel(const void* rows, const void* cols) {
    int i = blockIdx.x * blockDim.x + threadIdx.x;
    if (i >= N_EDGES) return;
    int r, c;
    if (g_idx64_flag) {
        r = (int)((const long long*)rows)[i];
        c = (int)((const long long*)cols)[i];
    } else {
        r = ((const int*)rows)[i];
        c = ((const int*)cols)[i];
    }
    g_rows[i] = r;
    g_cols[i] = c;
    atomicAdd(&g_cnt[r], 1u);
}

#define SCAN_THREADS 512
#define SCAN_PER_THREAD 98
__global__ __launch_bounds__(SCAN_THREADS) void scan_kernel() {
    __shared__ unsigned sums[SCAN_THREADS];
    const int t = threadIdx.x;
    const int base = t * SCAN_PER_THREAD;
    unsigned s = 0;
    for (int i = 0; i < SCAN_PER_THREAD; i++) {
        int idx = base + i;
        if (idx < N_NODES) s += g_cnt[idx];
    }
    sums[t] = s;
    __syncthreads();
    for (int off = 1; off < SCAN_THREADS; off <<= 1) {
        unsigned v = (t >= off) ? sums[t - off] : 0u;
        __syncthreads();
        sums[t] += v;
        __syncthreads();
    }
    unsigned run = (t == 0) ? 0u : sums[t - 1];
    for (int i = 0; i < SCAN_PER_THREAD; i++) {
        int idx = base + i;
        if (idx < N_NODES) {
            g_rowptr[idx] = run;
            g_cursor[idx] = run;
            run += g_cnt[idx];
        }
    }
    if (t == SCAN_THREADS - 1) g_rowptr[N_NODES] = run;
}

__global__ __launch_bounds__(256) void fill_kernel(const float* __restrict__ vals) {
    int i = blockIdx.x * blockDim.x + threadIdx.x;
    if (i >= N_EDGES) return;
    int r = g_rows[i];
    unsigned pos = atomicAdd(&g_cursor[r], 1u);
    g_csr[pos] = make_int2(g_cols[i], __float_as_int(vals[i]));
}

// ---------------- weight transpose + tf32 round: Wt[n][k] -------------------------
__global__ __launch_bounds__(256) void wprep_kernel(const float* __restrict__ W,
                                                    const float* __restrict__ Wg) {
    int i = blockIdx.x * blockDim.x + threadIdx.x;
    if (i >= 256 * 256) return;
    int n = i >> 8;
    int k = i & 255;
    float v = (n < 128) ? W[(size_t)k * OUT_CH + n] : Wg[(size_t)k * OUT_CH + (n - 128)];
    g_wt[(size_t)n * 256 + k] = f2tf32(v);
}

// ---------------- mma.sync tf32 dual GEMM, fp16 interleaved epilogue --------------
#define KC 16
#define AST 20
#define BST 20

__device__ __forceinline__ void mma_tf32(float c[4], const u32 a[4], const u32 b[2]) {
    asm volatile(
        "mma.sync.aligned.m16n8k8.row.col.f32.tf32.tf32.f32 "
        "{%0,%1,%2,%3}, {%4,%5,%6,%7}, {%8,%9}, {%0,%1,%2,%3};"
        : "+f"(c[0]), "+f"(c[1]), "+f"(c[2]), "+f"(c[3])
        : "r"(a[0]), "r"(a[1]), "r"(a[2]), "r"(a[3]), "r"(b[0]), "r"(b[1]));
}

__global__ __launch_bounds__(512) void gemm_kernel(const float* __restrict__ x) {
    __shared__ u32 As[128 * AST];
    __shared__ u32 Bs[256 * BST];

    const int tid    = threadIdx.x;
    const int wid    = tid >> 5;
    const int lane   = tid & 31;
    const int gid    = lane >> 2;
    const int tig    = lane & 3;
    const int warp_m = wid & 3;
    const int warp_n = wid >> 2;
    const int row0   = blockIdx.x * 128;

    float c[2][8][4];
#pragma unroll
    for (int mt = 0; mt < 2; mt++)
#pragma unroll
        for (int nt = 0; nt < 8; nt++)
#pragma unroll
            for (int q = 0; q < 4; q++) c[mt][nt][q] = 0.f;

    for (int k0 = 0; k0 < IN_CH; k0 += KC) {
        __syncthreads();
        {
            int m  = tid >> 2;
            int kk = (tid & 3) << 2;
            int gr = row0 + m;
            uint4 v = make_uint4(0u, 0u, 0u, 0u);
            if (gr < N_NODES) {
                float4 xv = *(const float4*)&x[(size_t)gr * IN_CH + k0 + kk];
                v.x = f2tf32(xv.x); v.y = f2tf32(xv.y);
                v.z = f2tf32(xv.z); v.w = f2tf32(xv.w);
            }
            *(uint4*)&As[m * AST + kk] = v;
        }
#pragma unroll
        for (int j = 0; j < 2; j++) {
            int e  = tid + j * 512;
            int n  = e >> 2;
            int kk = (e & 3) << 2;
            *(uint4*)&Bs[n * BST + kk] = *(const uint4*)&g_wt[(size_t)n * 256 + k0 + kk];
        }
        __syncthreads();

#pragma unroll
        for (int ks = 0; ks < KC / 8; ks++) {
            const int k = ks * 8;
            u32 a[2][4];
#pragma unroll
            for (int mt = 0; mt < 2; mt++) {
                const int m = warp_m * 32 + mt * 16;
                a[mt][0] = As[(m + gid) * AST + k + tig];
                a[mt][1] = As[(m + gid + 8) * AST + k + tig];
                a[mt][2] = As[(m + gid) * AST + k + tig + 4];
                a[mt][3] = As[(m + gid + 8) * AST + k + tig + 4];
            }
#pragma unroll
            for (int nt = 0; nt < 8; nt++) {
                const int n = warp_n * 64 + nt * 8;
                u32 b[2];
                b[0] = Bs[(n + gid) * BST + k + tig];
                b[1] = Bs[(n + gid) * BST + k + tig + 4];
                mma_tf32(c[0][nt], a[0], b);
                mma_tf32(c[1][nt], a[1], b);
            }
        }
    }

    // epilogue: write fp16 pairs into interleaved g_sg
    // chunk layout (half2 idx within row of 128): j*4 + {0:s01, 1:s23, 2:g01, 3:g23}
#pragma unroll
    for (int mt = 0; mt < 2; mt++) {
        const int m = row0 + warp_m * 32 + mt * 16 + gid;
#pragma unroll
        for (int nt = 0; nt < 8; nt++) {
            const int n  = warp_n * 64 + nt * 8 + 2 * tig;
            const int isg = (n >= 128) ? 2 : 0;
            const int nc  = n & 127;                     // even
            const int idx = (nc >> 2) * 4 + isg + ((nc & 2) >> 1);
            if (m < N_NODES)
                g_sg[(size_t)m * 128 + idx] =
                    __floats2half2_rn(c[mt][nt][0], c[mt][nt][1]);
            if (m + 8 < N_NODES)
                g_sg[(size_t)(m + 8) * 128 + idx] =
                    __floats2half2_rn(c[mt][nt][2], c[mt][nt][3]);
        }
    }
}

// ---------------- fused row SpMM + sigmoid gate: one warp per row -----------------
// lane handles chunk=lane -> cols 4lane..4lane+3 of support and gate.
__global__ __launch_bounds__(256) void spmm_kernel(float* __restrict__ out) {
    const int warp = (blockIdx.x * blockDim.x + threadIdx.x) >> 5;
    const int lane = threadIdx.x & 31;
    if (warp >= N_NODES) return;

    const int start = g_rowptr[warp];
    const int end   = g_rowptr[warp + 1];

    float4 aS = make_float4(0.f, 0.f, 0.f, 0.f);
    float4 aG = make_float4(0.f, 0.f, 0.f, 0.f);

    for (int e0 = start; e0 < end; e0 += 32) {
        const int n = min(32, end - e0);
        int2 ev = make_int2(0, 0);
        if (lane < n) ev = __ldg(&g_csr[e0 + lane]);

        int j = 0;
        for (; j + 8 <= n; j += 8) {
            uint4 L[8];
            float vv[8];
#pragma unroll
            for (int q = 0; q < 8; q++) {
                int cc = __shfl_sync(0xffffffffu, ev.x, j + q);
                vv[q]  = __int_as_float(__shfl_sync(0xffffffffu, ev.y, j + q));
                L[q] = *(const uint4*)&g_sg[(size_t)cc * 128 + lane * 4];
            }
#pragma unroll
            for (int q = 0; q < 8; q++) {
                float2 s01 = __half22float2(*(half2*)&L[q].x);
                float2 s23 = __half22float2(*(half2*)&L[q].y);
                float2 g01 = __half22float2(*(half2*)&L[q].z);
                float2 g23 = __half22float2(*(half2*)&L[q].w);
                float v0 = vv[q];
                aS.x += v0 * s01.x; aS.y += v0 * s01.y;
                aS.z += v0 * s23.x; aS.w += v0 * s23.y;
                aG.x += v0 * g01.x; aG.y += v0 * g01.y;
                aG.z += v0 * g23.x; aG.w += v0 * g23.y;
            }
        }
        for (; j < n; j++) {
            int   cc = __shfl_sync(0xffffffffu, ev.x, j);
            float v0 = __int_as_float(__shfl_sync(0xffffffffu, ev.y, j));
            uint4 Lq = *(const uint4*)&g_sg[(size_t)cc * 128 + lane * 4];
            float2 s01 = __half22float2(*(half2*)&Lq.x);
            float2 s23 = __half22float2(*(half2*)&Lq.y);
            float2 g01 = __half22float2(*(half2*)&Lq.z);
            float2 g23 = __half22float2(*(half2*)&Lq.w);
            aS.x += v0 * s01.x; aS.y += v0 * s01.y;
            aS.z += v0 * s23.x; aS.w += v0 * s23.y;
            aG.x += v0 * g01.x; aG.y += v0 * g01.y;
            aG.z += v0 * g23.x; aG.w += v0 * g23.y;
        }
    }

    float4 o;
    o.x = aS.x / (1.f + __expf(-aG.x));
    o.y = aS.y / (1.f + __expf(-aG.y));
    o.z = aS.z / (1.f + __expf(-aG.z));
    o.w = aS.w / (1.f + __expf(-aG.w));
    *(float4*)&out[(size_t)warp * OUT_CH + lane * 4] = o;
}

// ---------------- launch ----------------------------------------------------------
extern "C" void kernel_launch(void* const* d_in, const int* in_sizes, int n_in,
                              void* d_out, int out_size) {
    const float* x     = (const float*)d_in[0];
    const void*  erows = d_in[1];
    const void*  ecols = d_in[2];
    const float* evals = (const float*)d_in[3];
    const float* W     = (const float*)d_in[4];
    const float* Wg    = (const float*)d_in[5];
    float* out = (float*)d_out;

    init_kernel<<<(N_NODES + 255) / 256, 256>>>(erows, ecols);
    count_kernel<<<(N_EDGES + 255) / 256, 256>>>(erows, ecols);
    scan_kernel<<<1, SCAN_THREADS>>>();
    fill_kernel<<<(N_EDGES + 255) / 256, 256>>>(evals);

    wprep_kernel<<<(256 * 256 + 255) / 256, 256>>>(W, Wg);
    gemm_kernel<<<(N_NODES + 127) / 128, 512>>>(x);

    spmm_kernel<<<(N_NODES + 7) / 8, 256>>>(out);
}

// round 6
// speedup vs baseline: 2.2053x; 1.1069x over previous
#include <cuda_runtime.h>
#include <cuda_fp16.h>
#include <cstdint>

#define N_NODES 50000
#define IN_CH 256
#define OUT_CH 128
#define N_EDGES 800000

typedef unsigned long long u64;
typedef unsigned int u32;

// ---------------- scratch (static device globals; no allocation) ----------------
// g_sg layout: per node, 32 chunks of 16B; chunk j = {s[4j..4j+3], g[4j..4j+3]} fp16.
__device__ half2    g_sg[(size_t)N_NODES * 128];
__device__ u32      g_wt[256 * 256];               // combined [W|Wg]^T, tf32-rounded, [n][k]
__device__ int      g_rows[N_EDGES];
__device__ int      g_cols[N_EDGES];
__device__ unsigned g_cnt[N_NODES];
__device__ unsigned g_rowptr[N_NODES + 1];
__device__ unsigned g_cursor[N_NODES];
__device__ int2     g_csr[N_EDGES];                // (col, val-as-int) in CSR order
__device__ int      g_idx64_flag;

__device__ __forceinline__ u32 f2tf32(float f) {
    u32 r; asm("cvt.rna.tf32.f32 %0, %1;" : "=r"(r) : "f"(f)); return r;
}

// ---------------- init: zero g_cnt + index dtype detection ------------------------
__global__ __launch_bounds__(256) void init_kernel(const void* rows, const void* cols) {
    int i = blockIdx.x * blockDim.x + threadIdx.x;
    if (i < N_NODES) g_cnt[i] = 0u;
    if (i == 0) {
        const long long* r64 = (const long long*)rows;
        const long long* c64 = (const long long*)cols;
        int ok = 1;
        for (int j = 0; j < 16; j++) {
            long long a = r64[j], b = c64[j];
            if (a < 0 || a >= N_NODES) ok = 0;
            if (b < 0 || b >= N_NODES) ok = 0;
        }
        g_idx64_flag = ok;
    }
}

__global__ __launch_bounds__(256) void count_kernel(const void* rows, const void* cols) {
    int i = blockIdx.x * blockDim.x + threadIdx.x;
    if (i >= N_EDGES) return;
    int r, c;
    if (g_idx64_flag) {
        r = (int)((const long long*)rows)[i];
        c = (int)((const long long*)cols)[i];
    } else {
        r = ((const int*)rows)[i];
        c = ((const int*)cols)[i];
    }
    g_rows[i] = r;
    g_cols[i] = c;
    atomicAdd(&g_cnt[r], 1u);
}

#define SCAN_THREADS 1024
#define SCAN_PER_THREAD 49     // 1024*49 = 50176 >= 50000
__global__ __launch_bounds__(SCAN_THREADS) void scan_kernel() {
    __shared__ unsigned sums[SCAN_THREADS];
    const int t = threadIdx.x;
    const int base = t * SCAN_PER_THREAD;
    unsigned s = 0;
#pragma unroll 7
    for (int i = 0; i < SCAN_PER_THREAD; i++) {
        int idx = base + i;
        if (idx < N_NODES) s += g_cnt[idx];
    }
    sums[t] = s;
    __syncthreads();
    for (int off = 1; off < SCAN_THREADS; off <<= 1) {
        unsigned v = (t >= off) ? sums[t - off] : 0u;
        __syncthreads();
        sums[t] += v;
        __syncthreads();
    }
    unsigned run = (t == 0) ? 0u : sums[t - 1];
    for (int i = 0; i < SCAN_PER_THREAD; i++) {
        int idx = base + i;
        if (idx < N_NODES) {
            g_rowptr[idx] = run;
            g_cursor[idx] = run;
            run += g_cnt[idx];
        }
    }
    if (t == SCAN_THREADS - 1) g_rowptr[N_NODES] = run;
}

__global__ __launch_bounds__(256) void fill_kernel(const float* __restrict__ vals) {
    int i = blockIdx.x * blockDim.x + threadIdx.x;
    if (i >= N_EDGES) return;
    int r = g_rows[i];
    unsigned pos = atomicAdd(&g_cursor[r], 1u);
    g_csr[pos] = make_int2(g_cols[i], __float_as_int(vals[i]));
}

// ---------------- weight transpose + tf32 round: Wt[n][k] -------------------------
__global__ __launch_bounds__(256) void wprep_kernel(const float* __restrict__ W,
                                                    const float* __restrict__ Wg) {
    int i = blockIdx.x * blockDim.x + threadIdx.x;
    if (i >= 256 * 256) return;
    int n = i >> 8;
    int k = i & 255;
    float v = (n < 128) ? W[(size_t)k * OUT_CH + n] : Wg[(size_t)k * OUT_CH + (n - 128)];
    g_wt[(size_t)n * 256 + k] = f2tf32(v);
}

// ---------------- mma.sync tf32 dual GEMM, fp16 interleaved epilogue --------------
#define KC 16
#define AST 20
#define BST 20

__device__ __forceinline__ void mma_tf32(float c[4], const u32 a[4], const u32 b[2]) {
    asm volatile(
        "mma.sync.aligned.m16n8k8.row.col.f32.tf32.tf32.f32 "
        "{%0,%1,%2,%3}, {%4,%5,%6,%7}, {%8,%9}, {%0,%1,%2,%3};"
        : "+f"(c[0]), "+f"(c[1]), "+f"(c[2]), "+f"(c[3])
        : "r"(a[0]), "r"(a[1]), "r"(a[2]), "r"(a[3]), "r"(b[0]), "r"(b[1]));
}

__global__ __launch_bounds__(512) void gemm_kernel(const float* __restrict__ x) {
    __shared__ u32 As[128 * AST];
    __shared__ u32 Bs[256 * BST];

    const int tid    = threadIdx.x;
    const int wid    = tid >> 5;
    const int lane   = tid & 31;
    const int gid    = lane >> 2;
    const int tig    = lane & 3;
    const int warp_m = wid & 3;
    const int warp_n = wid >> 2;
    const int row0   = blockIdx.x * 128;

    float c[2][8][4];
#pragma unroll
    for (int mt = 0; mt < 2; mt++)
#pragma unroll
        for (int nt = 0; nt < 8; nt++)
#pragma unroll
            for (int q = 0; q < 4; q++) c[mt][nt][q] = 0.f;

    for (int k0 = 0; k0 < IN_CH; k0 += KC) {
        __syncthreads();
        {
            int m  = tid >> 2;
            int kk = (tid & 3) << 2;
            int gr = row0 + m;
            uint4 v = make_uint4(0u, 0u, 0u, 0u);
            if (gr < N_NODES) {
                float4 xv = *(const float4*)&x[(size_t)gr * IN_CH + k0 + kk];
                v.x = f2tf32(xv.x); v.y = f2tf32(xv.y);
                v.z = f2tf32(xv.z); v.w = f2tf32(xv.w);
            }
            *(uint4*)&As[m * AST + kk] = v;
        }
#pragma unroll
        for (int j = 0; j < 2; j++) {
            int e  = tid + j * 512;
            int n  = e >> 2;
            int kk = (e & 3) << 2;
            *(uint4*)&Bs[n * BST + kk] = *(const uint4*)&g_wt[(size_t)n * 256 + k0 + kk];
        }
        __syncthreads();

#pragma unroll
        for (int ks = 0; ks < KC / 8; ks++) {
            const int k = ks * 8;
            u32 a[2][4];
#pragma unroll
            for (int mt = 0; mt < 2; mt++) {
                const int m = warp_m * 32 + mt * 16;
                a[mt][0] = As[(m + gid) * AST + k + tig];
                a[mt][1] = As[(m + gid + 8) * AST + k + tig];
                a[mt][2] = As[(m + gid) * AST + k + tig + 4];
                a[mt][3] = As[(m + gid + 8) * AST + k + tig + 4];
            }
#pragma unroll
            for (int nt = 0; nt < 8; nt++) {
                const int n = warp_n * 64 + nt * 8;
                u32 b[2];
                b[0] = Bs[(n + gid) * BST + k + tig];
                b[1] = Bs[(n + gid) * BST + k + tig + 4];
                mma_tf32(c[0][nt], a[0], b);
                mma_tf32(c[1][nt], a[1], b);
            }
        }
    }

    // epilogue: write fp16 pairs into interleaved g_sg
#pragma unroll
    for (int mt = 0; mt < 2; mt++) {
        const int m = row0 + warp_m * 32 + mt * 16 + gid;
#pragma unroll
        for (int nt = 0; nt < 8; nt++) {
            const int n  = warp_n * 64 + nt * 8 + 2 * tig;
            const int isg = (n >= 128) ? 2 : 0;
            const int nc  = n & 127;
            const int idx = (nc >> 2) * 4 + isg + ((nc & 2) >> 1);
            if (m < N_NODES)
                g_sg[(size_t)m * 128 + idx] =
                    __floats2half2_rn(c[mt][nt][0], c[mt][nt][1]);
            if (m + 8 < N_NODES)
                g_sg[(size_t)(m + 8) * 128 + idx] =
                    __floats2half2_rn(c[mt][nt][2], c[mt][nt][3]);
        }
    }
}

// ---------------- fused row SpMM + sigmoid gate: one warp per row -----------------
// Warp-uniform edge loads (broadcast LDG, no shuffles); lane handles 16B chunk.
__device__ __forceinline__ void sg_fma(float4& aS, float4& aG, uint4 L, float v) {
    float2 s01 = __half22float2(*(half2*)&L.x);
    float2 s23 = __half22float2(*(half2*)&L.y);
    float2 g01 = __half22float2(*(half2*)&L.z);
    float2 g23 = __half22float2(*(half2*)&L.w);
    aS.x += v * s01.x; aS.y += v * s01.y;
    aS.z += v * s23.x; aS.w += v * s23.y;
    aG.x += v * g01.x; aG.y += v * g01.y;
    aG.z += v * g23.x; aG.w += v * g23.y;
}

__global__ __launch_bounds__(256) void spmm_kernel(float* __restrict__ out) {
    const int warp = (blockIdx.x * blockDim.x + threadIdx.x) >> 5;
    const int lane = threadIdx.x & 31;
    if (warp >= N_NODES) return;

    const int start = __ldg(&((const int*)g_rowptr)[warp]);
    const int end   = __ldg(&((const int*)g_rowptr)[warp + 1]);
    const u32 coff  = lane * 4;

    float4 aS = make_float4(0.f, 0.f, 0.f, 0.f);
    float4 aG = make_float4(0.f, 0.f, 0.f, 0.f);

    int e = start;
    // 8-wide: 8 uniform ev loads + 8 independent gathers in flight
    for (; e + 8 <= end; e += 8) {
        int2 ev[8];
#pragma unroll
        for (int q = 0; q < 8; q++) ev[q] = __ldg(&g_csr[e + q]);
        uint4 L[8];
#pragma unroll
        for (int q = 0; q < 8; q++)
            L[q] = *(const uint4*)&g_sg[(size_t)ev[q].x * 128 + coff];
#pragma unroll
        for (int q = 0; q < 8; q++)
            sg_fma(aS, aG, L[q], __int_as_float(ev[q].y));
    }
    if (e + 4 <= end) {
        int2 ev[4];
#pragma unroll
        for (int q = 0; q < 4; q++) ev[q] = __ldg(&g_csr[e + q]);
        uint4 L[4];
#pragma unroll
        for (int q = 0; q < 4; q++)
            L[q] = *(const uint4*)&g_sg[(size_t)ev[q].x * 128 + coff];
#pragma unroll
        for (int q = 0; q < 4; q++)
            sg_fma(aS, aG, L[q], __int_as_float(ev[q].y));
        e += 4;
    }
    for (; e < end; e++) {
        int2 ev = __ldg(&g_csr[e]);
        uint4 L = *(const uint4*)&g_sg[(size_t)ev.x * 128 + coff];
        sg_fma(aS, aG, L, __int_as_float(ev.y));
    }

    float4 o;
    o.x = aS.x / (1.f + __expf(-aG.x));
    o.y = aS.y / (1.f + __expf(-aG.y));
    o.z = aS.z / (1.f + __expf(-aG.z));
    o.w = aS.w / (1.f + __expf(-aG.w));
    *(float4*)&out[(size_t)warp * OUT_CH + lane * 4] = o;
}

// ---------------- launch: fork CSR branch || GEMM branch, join before spmm --------
extern "C" void kernel_launch(void* const* d_in, const int* in_sizes, int n_in,
                              void* d_out, int out_size) {
    const float* x     = (const float*)d_in[0];
    const void*  erows = d_in[1];
    const void*  ecols = d_in[2];
    const float* evals = (const float*)d_in[3];
    const float* W     = (const float*)d_in[4];
    const float* Wg    = (const float*)d_in[5];
    float* out = (float*)d_out;

    static cudaStream_t s2 = nullptr;
    static cudaEvent_t  ev_fork = nullptr, ev_join = nullptr;
    if (s2 == nullptr) {
        cudaStreamCreateWithFlags(&s2, cudaStreamNonBlocking);
        cudaEventCreateWithFlags(&ev_fork, cudaEventDisableTiming);
        cudaEventCreateWithFlags(&ev_join, cudaEventDisableTiming);
    }

    // fork: GEMM branch on s2
    cudaEventRecord(ev_fork, 0);
    cudaStreamWaitEvent(s2, ev_fork, 0);
    wprep_kernel<<<(256 * 256 + 255) / 256, 256, 0, s2>>>(W, Wg);
    gemm_kernel<<<(N_NODES + 127) / 128, 512, 0, s2>>>(x);
    cudaEventRecord(ev_join, s2);

    // CSR branch on the main stream
    init_kernel<<<(N_NODES + 255) / 256, 256>>>(erows, ecols);
    count_kernel<<<(N_EDGES + 255) / 256, 256>>>(erows, ecols);
    scan_kernel<<<1, SCAN_THREADS>>>();
    fill_kernel<<<(N_EDGES + 255) / 256, 256>>>(evals);

    // join + spmm
    cudaStreamWaitEvent(0, ev_join, 0);
    spmm_kernel<<<(N_NODES + 7) / 8, 256>>>(out);
}

// round 7
// speedup vs baseline: 2.2525x; 1.0214x over previous
#include <cuda_runtime.h>
#include <cuda_fp16.h>
#include <cstdint>

#define N_NODES 50000
#define IN_CH 256
#define OUT_CH 128
#define N_EDGES 800000

typedef unsigned long long u64;
typedef unsigned int u32;

// ---------------- scratch (static device globals; no allocation) ----------------
// g_sg layout: per node, 32 chunks of 16B; chunk j = {s[4j..4j+3], g[4j..4j+3]} fp16.
__device__ half2    g_sg[(size_t)N_NODES * 128];
__device__ u32      g_wt[256 * 256];               // combined [W|Wg]^T, tf32-rounded, [n][k]
__device__ int      g_rows[N_EDGES];
__device__ int      g_cols[N_EDGES];
__device__ unsigned g_cnt[N_NODES];
__device__ unsigned g_rowptr[N_NODES + 1];
__device__ unsigned g_cursor[N_NODES];
__device__ int2     g_csr[N_EDGES];                // (col, val-as-int) in CSR order
__device__ int      g_idx64_flag;

__device__ __forceinline__ u32 f2tf32(float f) {
    u32 r; asm("cvt.rna.tf32.f32 %0, %1;" : "=r"(r) : "f"(f)); return r;
}

// ---------------- init: zero g_cnt + weight prep + dtype detection ----------------
// 65536 threads: i zeroes g_cnt[i] (i<N), does one g_wt element, thread 0 detects.
__global__ __launch_bounds__(256) void initw_kernel(const void* rows, const void* cols,
                                                    const float* __restrict__ W,
                                                    const float* __restrict__ Wg) {
    int i = blockIdx.x * blockDim.x + threadIdx.x;   // 0..65535
    if (i < N_NODES) g_cnt[i] = 0u;
    {
        int n = i >> 8;          // 0..255 output col
        int k = i & 255;         // 0..255 input ch
        float v = (n < 128) ? W[(size_t)k * OUT_CH + n] : Wg[(size_t)k * OUT_CH + (n - 128)];
        g_wt[(size_t)n * 256 + k] = f2tf32(v);
    }
    if (i == 0) {
        const long long* r64 = (const long long*)rows;
        const long long* c64 = (const long long*)cols;
        int ok = 1;
        for (int j = 0; j < 16; j++) {
            long long a = r64[j], b = c64[j];
            if (a < 0 || a >= N_NODES) ok = 0;
            if (b < 0 || b >= N_NODES) ok = 0;
        }
        g_idx64_flag = ok;
    }
}

__global__ __launch_bounds__(256) void count_kernel(const void* rows, const void* cols) {
    int i = blockIdx.x * blockDim.x + threadIdx.x;
    if (i >= N_EDGES) return;
    int r, c;
    if (g_idx64_flag) {
        r = (int)((const long long*)rows)[i];
        c = (int)((const long long*)cols)[i];
    } else {
        r = ((const int*)rows)[i];
        c = ((const int*)cols)[i];
    }
    g_rows[i] = r;
    g_cols[i] = c;
    atomicAdd(&g_cnt[r], 1u);
}

#define SCAN_THREADS 1024
#define SCAN_PER_THREAD 49     // 1024*49 = 50176 >= 50000
__global__ __launch_bounds__(SCAN_THREADS) void scan_kernel() {
    __shared__ unsigned sums[SCAN_THREADS];
    const int t = threadIdx.x;
    const int base = t * SCAN_PER_THREAD;
    unsigned s = 0;
#pragma unroll 7
    for (int i = 0; i < SCAN_PER_THREAD; i++) {
        int idx = base + i;
        if (idx < N_NODES) s += g_cnt[idx];
    }
    sums[t] = s;
    __syncthreads();
    for (int off = 1; off < SCAN_THREADS; off <<= 1) {
        unsigned v = (t >= off) ? sums[t - off] : 0u;
        __syncthreads();
        sums[t] += v;
        __syncthreads();
    }
    unsigned run = (t == 0) ? 0u : sums[t - 1];
    for (int i = 0; i < SCAN_PER_THREAD; i++) {
        int idx = base + i;
        if (idx < N_NODES) {
            g_rowptr[idx] = run;
            g_cursor[idx] = run;
            run += g_cnt[idx];
        }
    }
    if (t == SCAN_THREADS - 1) g_rowptr[N_NODES] = run;
}

__global__ __launch_bounds__(256) void fill_kernel(const float* __restrict__ vals) {
    int i = blockIdx.x * blockDim.x + threadIdx.x;
    if (i >= N_EDGES) return;
    int r = g_rows[i];
    unsigned pos = atomicAdd(&g_cursor[r], 1u);
    g_csr[pos] = make_int2(g_cols[i], __float_as_int(vals[i]));
}

// ---------------- mma.sync tf32 dual GEMM, fp16 interleaved epilogue --------------
#define KC 16
#define AST 20
#define BST 20

__device__ __forceinline__ void mma_tf32(float c[4], const u32 a[4], const u32 b[2]) {
    asm volatile(
        "mma.sync.aligned.m16n8k8.row.col.f32.tf32.tf32.f32 "
        "{%0,%1,%2,%3}, {%4,%5,%6,%7}, {%8,%9}, {%0,%1,%2,%3};"
        : "+f"(c[0]), "+f"(c[1]), "+f"(c[2]), "+f"(c[3])
        : "r"(a[0]), "r"(a[1]), "r"(a[2]), "r"(a[3]), "r"(b[0]), "r"(b[1]));
}

__global__ __launch_bounds__(512) void gemm_kernel(const float* __restrict__ x) {
    __shared__ u32 As[128 * AST];
    __shared__ u32 Bs[256 * BST];

    const int tid    = threadIdx.x;
    const int wid    = tid >> 5;
    const int lane   = tid & 31;
    const int gid    = lane >> 2;
    const int tig    = lane & 3;
    const int warp_m = wid & 3;
    const int warp_n = wid >> 2;
    const int row0   = blockIdx.x * 128;

    float c[2][8][4];
#pragma unroll
    for (int mt = 0; mt < 2; mt++)
#pragma unroll
        for (int nt = 0; nt < 8; nt++)
#pragma unroll
            for (int q = 0; q < 4; q++) c[mt][nt][q] = 0.f;

    for (int k0 = 0; k0 < IN_CH; k0 += KC) {
        __syncthreads();
        {
            int m  = tid >> 2;
            int kk = (tid & 3) << 2;
            int gr = row0 + m;
            uint4 v = make_uint4(0u, 0u, 0u, 0u);
            if (gr < N_NODES) {
                float4 xv = *(const float4*)&x[(size_t)gr * IN_CH + k0 + kk];
                v.x = f2tf32(xv.x); v.y = f2tf32(xv.y);
                v.z = f2tf32(xv.z); v.w = f2tf32(xv.w);
            }
            *(uint4*)&As[m * AST + kk] = v;
        }
#pragma unroll
        for (int j = 0; j < 2; j++) {
            int e  = tid + j * 512;
            int n  = e >> 2;
            int kk = (e & 3) << 2;
            *(uint4*)&Bs[n * BST + kk] = *(const uint4*)&g_wt[(size_t)n * 256 + k0 + kk];
        }
        __syncthreads();

#pragma unroll
        for (int ks = 0; ks < KC / 8; ks++) {
            const int k = ks * 8;
            u32 a[2][4];
#pragma unroll
            for (int mt = 0; mt < 2; mt++) {
                const int m = warp_m * 32 + mt * 16;
                a[mt][0] = As[(m + gid) * AST + k + tig];
                a[mt][1] = As[(m + gid + 8) * AST + k + tig];
                a[mt][2] = As[(m + gid) * AST + k + tig + 4];
                a[mt][3] = As[(m + gid + 8) * AST + k + tig + 4];
            }
#pragma unroll
            for (int nt = 0; nt < 8; nt++) {
                const int n = warp_n * 64 + nt * 8;
                u32 b[2];
                b[0] = Bs[(n + gid) * BST + k + tig];
                b[1] = Bs[(n + gid) * BST + k + tig + 4];
                mma_tf32(c[0][nt], a[0], b);
                mma_tf32(c[1][nt], a[1], b);
            }
        }
    }

    // epilogue: write fp16 pairs into interleaved g_sg
#pragma unroll
    for (int mt = 0; mt < 2; mt++) {
        const int m = row0 + warp_m * 32 + mt * 16 + gid;
#pragma unroll
        for (int nt = 0; nt < 8; nt++) {
            const int n  = warp_n * 64 + nt * 8 + 2 * tig;
            const int isg = (n >= 128) ? 2 : 0;
            const int nc  = n & 127;
            const int idx = (nc >> 2) * 4 + isg + ((nc & 2) >> 1);
            if (m < N_NODES)
                g_sg[(size_t)m * 128 + idx] =
                    __floats2half2_rn(c[mt][nt][0], c[mt][nt][1]);
            if (m + 8 < N_NODES)
                g_sg[(size_t)(m + 8) * 128 + idx] =
                    __floats2half2_rn(c[mt][nt][2], c[mt][nt][3]);
        }
    }
}

// ---------------- fused row SpMM + sigmoid gate: TWO warps per row ----------------
// Warp pair (h=0,1) splits the row's edge range contiguously; partial sums combined
// through smem. 12500 blocks x 4 rows, no remainder -> uniform __syncthreads.
__device__ __forceinline__ void sg_fma(float4& aS, float4& aG, uint4 L, float v) {
    float2 s01 = __half22float2(*(half2*)&L.x);
    float2 s23 = __half22float2(*(half2*)&L.y);
    float2 g01 = __half22float2(*(half2*)&L.z);
    float2 g23 = __half22float2(*(half2*)&L.w);
    aS.x += v * s01.x; aS.y += v * s01.y;
    aS.z += v * s23.x; aS.w += v * s23.y;
    aG.x += v * g01.x; aG.y += v * g01.y;
    aG.z += v * g23.x; aG.w += v * g23.y;
}

__global__ __launch_bounds__(256) void spmm_kernel(float* __restrict__ out) {
    __shared__ float4 red[4][2][32];   // [row-in-block][S/G][lane]

    const int wid   = threadIdx.x >> 5;
    const int lane  = threadIdx.x & 31;
    const int rloc  = wid >> 1;        // 0..3
    const int h     = wid & 1;
    const int row   = blockIdx.x * 4 + rloc;   // always < N_NODES (12500*4 = 50000)

    const int rs  = __ldg(&((const int*)g_rowptr)[row]);
    const int re  = __ldg(&((const int*)g_rowptr)[row + 1]);
    const int len = re - rs;
    const int hf  = (len + 1) >> 1;
    const int s   = rs + h * hf;
    const int end = h ? re : rs + hf;
    const u32 coff = lane * 4;

    float4 aS = make_float4(0.f, 0.f, 0.f, 0.f);
    float4 aG = make_float4(0.f, 0.f, 0.f, 0.f);

    int e = s;
    for (; e + 8 <= end; e += 8) {
        int2 ev[8];
#pragma unroll
        for (int q = 0; q < 8; q++) ev[q] = __ldg(&g_csr[e + q]);
        uint4 L[8];
#pragma unroll
        for (int q = 0; q < 8; q++)
            L[q] = *(const uint4*)&g_sg[(size_t)ev[q].x * 128 + coff];
#pragma unroll
        for (int q = 0; q < 8; q++)
            sg_fma(aS, aG, L[q], __int_as_float(ev[q].y));
    }
    if (e + 4 <= end) {
        int2 ev[4];
#pragma unroll
        for (int q = 0; q < 4; q++) ev[q] = __ldg(&g_csr[e + q]);
        uint4 L[4];
#pragma unroll
        for (int q = 0; q < 4; q++)
            L[q] = *(const uint4*)&g_sg[(size_t)ev[q].x * 128 + coff];
#pragma unroll
        for (int q = 0; q < 4; q++)
            sg_fma(aS, aG, L[q], __int_as_float(ev[q].y));
        e += 4;
    }
    for (; e < end; e++) {
        int2 ev = __ldg(&g_csr[e]);
        uint4 L = *(const uint4*)&g_sg[(size_t)ev.x * 128 + coff];
        sg_fma(aS, aG, L, __int_as_float(ev.y));
    }

    if (h) {
        red[rloc][0][lane] = aS;
        red[rloc][1][lane] = aG;
    }
    __syncthreads();
    if (!h) {
        float4 bS = red[rloc][0][lane];
        float4 bG = red[rloc][1][lane];
        aS.x += bS.x; aS.y += bS.y; aS.z += bS.z; aS.w += bS.w;
        aG.x += bG.x; aG.y += bG.y; aG.z += bG.z; aG.w += bG.w;
        float4 o;
        o.x = aS.x / (1.f + __expf(-aG.x));
        o.y = aS.y / (1.f + __expf(-aG.y));
        o.z = aS.z / (1.f + __expf(-aG.z));
        o.w = aS.w / (1.f + __expf(-aG.w));
        *(float4*)&out[(size_t)row * OUT_CH + coff] = o;
    }
}

// ---------------- launch: fork CSR branch || GEMM branch, join before spmm --------
extern "C" void kernel_launch(void* const* d_in, const int* in_sizes, int n_in,
                              void* d_out, int out_size) {
    const float* x     = (const float*)d_in[0];
    const void*  erows = d_in[1];
    const void*  ecols = d_in[2];
    const float* evals = (const float*)d_in[3];
    const float* W     = (const float*)d_in[4];
    const float* Wg    = (const float*)d_in[5];
    float* out = (float*)d_out;

    static cudaStream_t s2 = nullptr;
    static cudaEvent_t  ev_fork = nullptr, ev_join = nullptr;
    if (s2 == nullptr) {
        cudaStreamCreateWithFlags(&s2, cudaStreamNonBlocking);
        cudaEventCreateWithFlags(&ev_fork, cudaEventDisableTiming);
        cudaEventCreateWithFlags(&ev_join, cudaEventDisableTiming);
    }

    // shared root: zero cnt + weight prep + dtype detect
    initw_kernel<<<256, 256>>>(erows, ecols, W, Wg);

    // fork: GEMM branch on s2
    cudaEventRecord(ev_fork, 0);
    cudaStreamWaitEvent(s2, ev_fork, 0);
    gemm_kernel<<<(N_NODES + 127) / 128, 512, 0, s2>>>(x);
    cudaEventRecord(ev_join, s2);

    // CSR branch on the main stream
    count_kernel<<<(N_EDGES + 255) / 256, 256>>>(erows, ecols);
    scan_kernel<<<1, SCAN_THREADS>>>();
    fill_kernel<<<(N_EDGES + 255) / 256, 256>>>(evals);

    // join + spmm (2 warps/row)
    cudaStreamWaitEvent(0, ev_join, 0);
    spmm_kernel<<<N_NODES / 4, 256>>>(out);
}

// round 8
// speedup vs baseline: 3.4654x; 1.5385x over previous
#include <cuda_runtime.h>
#include <cuda_fp16.h>
#include <cstdint>

#define N_NODES 50000
#define IN_CH 256
#define OUT_CH 128
#define N_EDGES 800000

typedef unsigned long long u64;
typedef unsigned int u32;

#define SCAN_BLOCKS 196        // 196*256 = 50176 >= 50000

// ---------------- scratch (static device globals; no allocation) ----------------
// g_sg layout: per node, 32 chunks of 16B; chunk j = {s[4j..4j+3], g[4j..4j+3]} fp16.
__device__ half2    g_sg[(size_t)N_NODES * 128];
__device__ u32      g_wt[256 * 256];               // combined [W|Wg]^T, tf32-rounded, [n][k]
__device__ int      g_rows[N_EDGES];
__device__ int      g_cols[N_EDGES];
__device__ unsigned g_cnt[N_NODES];
__device__ unsigned g_scan[SCAN_BLOCKS * 256];     // block-local exclusive scans
__device__ unsigned g_bsum[SCAN_BLOCKS];           // per-block totals
__device__ unsigned g_boff[SCAN_BLOCKS];           // per-block exclusive offsets
__device__ unsigned g_rowptr[N_NODES + 1];
__device__ unsigned g_cursor[N_NODES];
__device__ int2     g_csr[N_EDGES];                // (col, val-as-int) in CSR order
__device__ int      g_idx64_flag;

__device__ __forceinline__ u32 f2tf32(float f) {
    u32 r; asm("cvt.rna.tf32.f32 %0, %1;" : "=r"(r) : "f"(f)); return r;
}

// ---------------- init: zero g_cnt + weight prep + dtype detection ----------------
__global__ __launch_bounds__(256) void initw_kernel(const void* rows, const void* cols,
                                                    const float* __restrict__ W,
                                                    const float* __restrict__ Wg) {
    int i = blockIdx.x * blockDim.x + threadIdx.x;   // 0..65535
    if (i < N_NODES) g_cnt[i] = 0u;
    {
        int n = i >> 8;
        int k = i & 255;
        float v = (n < 128) ? W[(size_t)k * OUT_CH + n] : Wg[(size_t)k * OUT_CH + (n - 128)];
        g_wt[(size_t)n * 256 + k] = f2tf32(v);
    }
    if (i == 0) {
        const long long* r64 = (const long long*)rows;
        const long long* c64 = (const long long*)cols;
        int ok = 1;
        for (int j = 0; j < 16; j++) {
            long long a = r64[j], b = c64[j];
            if (a < 0 || a >= N_NODES) ok = 0;
            if (b < 0 || b >= N_NODES) ok = 0;
        }
        g_idx64_flag = ok;
    }
}

__global__ __launch_bounds__(256) void count_kernel(const void* rows, const void* cols) {
    int i = blockIdx.x * blockDim.x + threadIdx.x;
    if (i >= N_EDGES) return;
    int r, c;
    if (g_idx64_flag) {
        r = (int)((const long long*)rows)[i];
        c = (int)((const long long*)cols)[i];
    } else {
        r = ((const int*)rows)[i];
        c = ((const int*)cols)[i];
    }
    g_rows[i] = r;
    g_cols[i] = c;
    atomicAdd(&g_cnt[r], 1u);
}

// ---------------- 3-phase full-chip scan -----------------------------------------
__global__ __launch_bounds__(256) void scan1_kernel() {
    __shared__ unsigned sm[256];
    const int t = threadIdx.x;
    const int i = blockIdx.x * 256 + t;
    unsigned v = (i < N_NODES) ? g_cnt[i] : 0u;
    sm[t] = v;
    __syncthreads();
#pragma unroll
    for (int off = 1; off < 256; off <<= 1) {
        unsigned u = (t >= off) ? sm[t - off] : 0u;
        __syncthreads();
        sm[t] += u;
        __syncthreads();
    }
    g_scan[blockIdx.x * 256 + t] = sm[t] - v;     // exclusive
    if (t == 255) g_bsum[blockIdx.x] = sm[255];
}

__global__ __launch_bounds__(256) void scan2_kernel() {
    __shared__ unsigned sm[256];
    const int t = threadIdx.x;
    unsigned v = (t < SCAN_BLOCKS) ? g_bsum[t] : 0u;
    sm[t] = v;
    __syncthreads();
#pragma unroll
    for (int off = 1; off < 256; off <<= 1) {
        unsigned u = (t >= off) ? sm[t - off] : 0u;
        __syncthreads();
        sm[t] += u;
        __syncthreads();
    }
    if (t < SCAN_BLOCKS) g_boff[t] = sm[t] - v;
    if (t == SCAN_BLOCKS - 1) g_rowptr[N_NODES] = sm[t];
}

__global__ __launch_bounds__(256) void scan3_kernel() {
    const int i = blockIdx.x * 256 + threadIdx.x;
    if (i >= N_NODES) return;
    unsigned r = g_boff[blockIdx.x] + g_scan[i];
    g_rowptr[i] = r;
    g_cursor[i] = r;
}

__global__ __launch_bounds__(256) void fill_kernel(const float* __restrict__ vals) {
    int i = blockIdx.x * blockDim.x + threadIdx.x;
    if (i >= N_EDGES) return;
    int r = g_rows[i];
    unsigned pos = atomicAdd(&g_cursor[r], 1u);
    g_csr[pos] = make_int2(g_cols[i], __float_as_int(vals[i]));
}

// ---------------- mma.sync tf32 dual GEMM, fp16 interleaved epilogue --------------
#define KC 16
#define AST 20
#define BST 20

__device__ __forceinline__ void mma_tf32(float c[4], const u32 a[4], const u32 b[2]) {
    asm volatile(
        "mma.sync.aligned.m16n8k8.row.col.f32.tf32.tf32.f32 "
        "{%0,%1,%2,%3}, {%4,%5,%6,%7}, {%8,%9}, {%0,%1,%2,%3};"
        : "+f"(c[0]), "+f"(c[1]), "+f"(c[2]), "+f"(c[3])
        : "r"(a[0]), "r"(a[1]), "r"(a[2]), "r"(a[3]), "r"(b[0]), "r"(b[1]));
}

__global__ __launch_bounds__(512) void gemm_kernel(const float* __restrict__ x) {
    __shared__ u32 As[128 * AST];
    __shared__ u32 Bs[256 * BST];

    const int tid    = threadIdx.x;
    const int wid    = tid >> 5;
    const int lane   = tid & 31;
    const int gid    = lane >> 2;
    const int tig    = lane & 3;
    const int warp_m = wid & 3;
    const int warp_n = wid >> 2;
    const int row0   = blockIdx.x * 128;

    float c[2][8][4];
#pragma unroll
    for (int mt = 0; mt < 2; mt++)
#pragma unroll
        for (int nt = 0; nt < 8; nt++)
#pragma unroll
            for (int q = 0; q < 4; q++) c[mt][nt][q] = 0.f;

    for (int k0 = 0; k0 < IN_CH; k0 += KC) {
        __syncthreads();
        {
            int m  = tid >> 2;
            int kk = (tid & 3) << 2;
            int gr = row0 + m;
            uint4 v = make_uint4(0u, 0u, 0u, 0u);
            if (gr < N_NODES) {
                float4 xv = *(const float4*)&x[(size_t)gr * IN_CH + k0 + kk];
                v.x = f2tf32(xv.x); v.y = f2tf32(xv.y);
                v.z = f2tf32(xv.z); v.w = f2tf32(xv.w);
            }
            *(uint4*)&As[m * AST + kk] = v;
        }
#pragma unroll
        for (int j = 0; j < 2; j++) {
            int e  = tid + j * 512;
            int n  = e >> 2;
            int kk = (e & 3) << 2;
            *(uint4*)&Bs[n * BST + kk] = *(const uint4*)&g_wt[(size_t)n * 256 + k0 + kk];
        }
        __syncthreads();

#pragma unroll
        for (int ks = 0; ks < KC / 8; ks++) {
            const int k = ks * 8;
            u32 a[2][4];
#pragma unroll
            for (int mt = 0; mt < 2; mt++) {
                const int m = warp_m * 32 + mt * 16;
                a[mt][0] = As[(m + gid) * AST + k + tig];
                a[mt][1] = As[(m + gid + 8) * AST + k + tig];
                a[mt][2] = As[(m + gid) * AST + k + tig + 4];
                a[mt][3] = As[(m + gid + 8) * AST + k + tig + 4];
            }
#pragma unroll
            for (int nt = 0; nt < 8; nt++) {
                const int n = warp_n * 64 + nt * 8;
                u32 b[2];
                b[0] = Bs[(n + gid) * BST + k + tig];
                b[1] = Bs[(n + gid) * BST + k + tig + 4];
                mma_tf32(c[0][nt], a[0], b);
                mma_tf32(c[1][nt], a[1], b);
            }
        }
    }

#pragma unroll
    for (int mt = 0; mt < 2; mt++) {
        const int m = row0 + warp_m * 32 + mt * 16 + gid;
#pragma unroll
        for (int nt = 0; nt < 8; nt++) {
            const int n  = warp_n * 64 + nt * 8 + 2 * tig;
            const int isg = (n >= 128) ? 2 : 0;
            const int nc  = n & 127;
            const int idx = (nc >> 2) * 4 + isg + ((nc & 2) >> 1);
            if (m < N_NODES)
                g_sg[(size_t)m * 128 + idx] =
                    __floats2half2_rn(c[mt][nt][0], c[mt][nt][1]);
            if (m + 8 < N_NODES)
                g_sg[(size_t)(m + 8) * 128 + idx] =
                    __floats2half2_rn(c[mt][nt][2], c[mt][nt][3]);
        }
    }
}

// ---------------- fused row SpMM + sigmoid gate: TWO warps per row ----------------
__device__ __forceinline__ void sg_fma(float4& aS, float4& aG, uint4 L, float v) {
    float2 s01 = __half22float2(*(half2*)&L.x);
    float2 s23 = __half22float2(*(half2*)&L.y);
    float2 g01 = __half22float2(*(half2*)&L.z);
    float2 g23 = __half22float2(*(half2*)&L.w);
    aS.x += v * s01.x; aS.y += v * s01.y;
    aS.z += v * s23.x; aS.w += v * s23.y;
    aG.x += v * g01.x; aG.y += v * g01.y;
    aG.z += v * g23.x; aG.w += v * g23.y;
}

__global__ __launch_bounds__(256) void spmm_kernel(float* __restrict__ out) {
    __shared__ float4 red[4][2][32];   // [row-in-block][S/G][lane]

    const int wid   = threadIdx.x >> 5;
    const int lane  = threadIdx.x & 31;
    const int rloc  = wid >> 1;        // 0..3
    const int h     = wid & 1;
    const int row   = blockIdx.x * 4 + rloc;   // 12500*4 = 50000 exactly

    const int rs  = __ldg(&((const int*)g_rowptr)[row]);
    const int re  = __ldg(&((const int*)g_rowptr)[row + 1]);
    const int len = re - rs;
    const int hf  = (len + 1) >> 1;
    const int s   = rs + h * hf;
    const int end = h ? re : rs + hf;
    const u32 coff = lane * 4;

    float4 aS = make_float4(0.f, 0.f, 0.f, 0.f);
    float4 aG = make_float4(0.f, 0.f, 0.f, 0.f);

    int e = s;
    for (; e + 8 <= end; e += 8) {
        int2 ev[8];
#pragma unroll
        for (int q = 0; q < 8; q++) ev[q] = __ldg(&g_csr[e + q]);
        uint4 L[8];
#pragma unroll
        for (int q = 0; q < 8; q++)
            L[q] = *(const uint4*)&g_sg[(size_t)ev[q].x * 128 + coff];
#pragma unroll
        for (int q = 0; q < 8; q++)
            sg_fma(aS, aG, L[q], __int_as_float(ev[q].y));
    }
    if (e + 4 <= end) {
        int2 ev[4];
#pragma unroll
        for (int q = 0; q < 4; q++) ev[q] = __ldg(&g_csr[e + q]);
        uint4 L[4];
#pragma unroll
        for (int q = 0; q < 4; q++)
            L[q] = *(const uint4*)&g_sg[(size_t)ev[q].x * 128 + coff];
#pragma unroll
        for (int q = 0; q < 4; q++)
            sg_fma(aS, aG, L[q], __int_as_float(ev[q].y));
        e += 4;
    }
    for (; e < end; e++) {
        int2 ev = __ldg(&g_csr[e]);
        uint4 L = *(const uint4*)&g_sg[(size_t)ev.x * 128 + coff];
        sg_fma(aS, aG, L, __int_as_float(ev.y));
    }

    if (h) {
        red[rloc][0][lane] = aS;
        red[rloc][1][lane] = aG;
    }
    __syncthreads();
    if (!h) {
        float4 bS = red[rloc][0][lane];
        float4 bG = red[rloc][1][lane];
        aS.x += bS.x; aS.y += bS.y; aS.z += bS.z; aS.w += bS.w;
        aG.x += bG.x; aG.y += bG.y; aG.z += bG.z; aG.w += bG.w;
        float4 o;
        o.x = aS.x / (1.f + __expf(-aG.x));
        o.y = aS.y / (1.f + __expf(-aG.y));
        o.z = aS.z / (1.f + __expf(-aG.z));
        o.w = aS.w / (1.f + __expf(-aG.w));
        *(float4*)&out[(size_t)row * OUT_CH + coff] = o;
    }
}

// ---------------- launch: fork CSR branch || GEMM branch, join before spmm --------
extern "C" void kernel_launch(void* const* d_in, const int* in_sizes, int n_in,
                              void* d_out, int out_size) {
    const float* x     = (const float*)d_in[0];
    const void*  erows = d_in[1];
    const void*  ecols = d_in[2];
    const float* evals = (const float*)d_in[3];
    const float* W     = (const float*)d_in[4];
    const float* Wg    = (const float*)d_in[5];
    float* out = (float*)d_out;

    static cudaStream_t s2 = nullptr;
    static cudaEvent_t  ev_fork = nullptr, ev_join = nullptr;
    if (s2 == nullptr) {
        cudaStreamCreateWithFlags(&s2, cudaStreamNonBlocking);
        cudaEventCreateWithFlags(&ev_fork, cudaEventDisableTiming);
        cudaEventCreateWithFlags(&ev_join, cudaEventDisableTiming);
    }

    // shared root: zero cnt + weight prep + dtype detect
    initw_kernel<<<256, 256>>>(erows, ecols, W, Wg);

    // fork: GEMM branch on s2
    cudaEventRecord(ev_fork, 0);
    cudaStreamWaitEvent(s2, ev_fork, 0);
    gemm_kernel<<<(N_NODES + 127) / 128, 512, 0, s2>>>(x);
    cudaEventRecord(ev_join, s2);

    // CSR branch on the main stream
    count_kernel<<<(N_EDGES + 255) / 256, 256>>>(erows, ecols);
    scan1_kernel<<<SCAN_BLOCKS, 256>>>();
    scan2_kernel<<<1, 256>>>();
    scan3_kernel<<<SCAN_BLOCKS, 256>>>();
    fill_kernel<<<(N_EDGES + 255) / 256, 256>>>(evals);

    // join + spmm (2 warps/row)
    cudaStreamWaitEvent(0, ev_join, 0);
    spmm_kernel<<<N_NODES / 4, 256>>>(out);
}